// round 16
// baseline (speedup 1.0000x reference)
#include <cuda_runtime.h>
#include <cuda_bf16.h>
#include <cuda_pipeline.h>
#include <math.h>

// SwitchMoE with the reference's dim-1 scatter gate bug:
//   mask[b, top1[b,n], 0] = 1  =>  output nonzero only for n<8, expert 0.
// E=8, DIM=128, HID=512, OUT=128, B=16, H=W=64, N=4096.
//
// 2 launches:
//   K1 (grid 640 x 128thr): blocks <512 = warp-autonomous gate (4-stage
//       cp.async.cg ring, FFMA2 packed accumulators) + interleaved streaming
//       zero-stores of out; blocks >=512 = expert-0 fc1 at 18 pixels/batch.
//   K2 (grid 32 x 512thr): block = (batch b, j-half). 4 rows/block, W2
//       streamed ONCE per block (aggregate L2 traffic 8 MB, was 32 MB);
//       rows packed in pairs into fma.rn.f32x2 accumulators.

#define BATCH 16
#define NTOK  4096
#define DIM   128
#define NEXP  8
#define HID   512
#define OUTD  128
#define EPS   1e-6f

// ---- scratch (device globals; every element rewritten each call) ----
__device__ unsigned g_bm[512];                    // per-gate-block OR of (1<<argmax)
__device__ float    g_prob0[BATCH * NEXP];        // softmax p(expert0) at token n<8
__device__ float    g_h1[BATCH * 2 * 9 * HID];    // expert-0 fc1 at (h in {0,1}, w in [0,9))

#define FMA2(acc, a, b) \
    asm("fma.rn.f32x2 %0, %1, %2, %0;" : "+l"(acc) : "l"(a), "l"(b))

// cp.async.cg: 16B global->shared, L2-only (no L1 allocate) — streaming reads
__device__ __forceinline__ void cp_cg16(void* dst_smem, const void* src) {
    unsigned d = (unsigned)__cvta_generic_to_shared(dst_smem);
    asm volatile("cp.async.cg.shared.global [%0], [%1], 16;" :: "r"(d), "l"(src));
}

// evict-first streaming store (dead data: nobody reads the zeros back)
__device__ __forceinline__ void stg_cs_zero(float4* p) {
    asm volatile("st.global.cs.v4.f32 [%0], {%1,%1,%1,%1};" :: "l"(p), "f"(0.0f));
}

// ------------------------------------------------------------------
// K1: warp-autonomous gate (+ interleaved streaming zeroing) and fc1
// ------------------------------------------------------------------
__global__ void __launch_bounds__(128, 5) gate_fc1_kernel(
    const float* __restrict__ x, const float* __restrict__ wg,
    const float* __restrict__ bg, const float* __restrict__ W1,
    const float* __restrict__ B1, float* __restrict__ out)
{
    // pool aliasing:
    //   gate: wg_s[1024] | bg_s[8] | xs[4 warps][4 stages][32*20] = 11272 floats
    //   fc1 : xs18[18*128] = 2304 floats
    __shared__ float pool[11272];
    __shared__ unsigned warpor[4];

    const int tid = threadIdx.x;
    const int blk = blockIdx.x;

    if (blk < 512) {
        // ================= gate path =================
        float* wg_s = pool;                          // [DIM*NEXP]
        float* bg_s = pool + 1024;                   // [NEXP]
        const int wid = tid >> 5, lane = tid & 31;
        float* xw = pool + 1032 + wid * (4 * 640);   // this warp's 4-stage ring

        const int tok0 = blk * 128;
        const float* xb = x + (size_t)(tok0 + wid * 32) * DIM;  // warp's 32 tokens
        float4* ob = (float4*)(out + (size_t)tok0 * OUTD);      // block's 128 out rows

        for (int i = tid; i < DIM * NEXP; i += 128) wg_s[i] = wg[i];
        if (tid < NEXP) bg_s[tid] = bg[tid];
        __syncthreads();                             // wg_s ready; warps go autonomous

        // staging coords: lane copies quarter q of tokens tq, tq+8, tq+16, tq+24
        const int tq = lane >> 2, q = lane & 3;

        // prologue: stage chunks 0..2 (each chunk = 32 tokens x 16 dims)
#pragma unroll
        for (int ch = 0; ch < 3; ch++) {
            float* dst = xw + ch * 640;
#pragma unroll
            for (int k = 0; k < 4; k++) {
                int t = tq + 8 * k;
                cp_cg16(dst + t * 20 + q * 4,
                        xb + (size_t)t * DIM + ch * 16 + q * 4);
            }
            __pipeline_commit();
        }

        // packed accumulators: (e0,e1) (e2,e3) (e4,e5) (e6,e7)
        unsigned long long a01 = 0ull, a23 = 0ull, a45 = 0ull, a67 = 0ull;

#pragma unroll
        for (int ch = 0; ch < 8; ch++) {
            if (ch < 5) {                            // stage chunk ch+3
                float* dst = xw + ((ch + 3) & 3) * 640;
#pragma unroll
                for (int k = 0; k < 4; k++) {
                    int t = tq + 8 * k;
                    cp_cg16(dst + t * 20 + q * 4,
                            xb + (size_t)t * DIM + (ch + 3) * 16 + q * 4);
                }
                __pipeline_commit();
                __pipeline_wait_prior(3);            // chunk ch landed
            } else {
                __pipeline_wait_prior(7 - ch);
            }
            __syncwarp();

            const float* buf = xw + (ch & 3) * 640;
#pragma unroll
            for (int d4 = 0; d4 < 4; d4++) {
                float4 xv = *(const float4*)(buf + lane * 20 + d4 * 4);
                float xarr[4] = {xv.x, xv.y, xv.z, xv.w};
#pragma unroll
                for (int jj = 0; jj < 4; jj++) {
                    int dd = ch * 16 + d4 * 4 + jj;
                    const ulonglong2* wrow = (const ulonglong2*)(wg_s + dd * 8);
                    ulonglong2 wa = wrow[0];
                    ulonglong2 wb = wrow[1];
                    unsigned long long xd2;
                    asm("mov.b64 %0, {%1, %1};" : "=l"(xd2) : "f"(xarr[jj]));
                    FMA2(a01, xd2, wa.x);
                    FMA2(a23, xd2, wa.y);
                    FMA2(a45, xd2, wb.x);
                    FMA2(a67, xd2, wb.y);
                }
            }
            __syncwarp();                            // done reading buf before re-fill

            // interleaved streaming zero-stores: 4 float4 per thread per chunk
#pragma unroll
            for (int k = 0; k < 4; k++)
                stg_cs_zero(ob + ch * 512 + k * 128 + tid);
        }

        // unpack logits, add bias; first-max argmax (matches jnp.argmax)
        float l[NEXP];
        asm("mov.b64 {%0, %1}, %2;" : "=f"(l[0]), "=f"(l[1]) : "l"(a01));
        asm("mov.b64 {%0, %1}, %2;" : "=f"(l[2]), "=f"(l[3]) : "l"(a23));
        asm("mov.b64 {%0, %1}, %2;" : "=f"(l[4]), "=f"(l[5]) : "l"(a45));
        asm("mov.b64 {%0, %1}, %2;" : "=f"(l[6]), "=f"(l[7]) : "l"(a67));
#pragma unroll
        for (int e = 0; e < NEXP; e++) l[e] += bg_s[e];
        float m = l[0]; int am = 0;
#pragma unroll
        for (int e = 1; e < NEXP; e++) if (l[e] > m) { m = l[e]; am = e; }

        const int tok = tok0 + tid;                  // wid*32+lane == tid
        const int b = tok >> 12;
        const int n = tok & (NTOK - 1);
        if (n < NEXP) {
            float s = 0.0f;
#pragma unroll
            for (int e = 0; e < NEXP; e++) s += expf(l[e] - m);
            g_prob0[b * NEXP + n] = expf(l[0] - m) / s;
        }

        // per-block argmax bitmask (replay-safe: every slot rewritten each call)
        unsigned wor = __reduce_or_sync(0xffffffffu, 1u << am);
        if (lane == 0) warpor[wid] = wor;
        __syncthreads();
        if (tid == 0)
            g_bm[blk] = warpor[0] | warpor[1] | warpor[2] | warpor[3];
    } else {
        // ================= fc1 path =================
        // expert-0 fc1 at 18 pixels/batch: h in {0,1}, w in [0,9)
        float* xs = pool;                            // [18*DIM]
        const int bb = blk - 512;                    // [0,128)
        const int b  = bb >> 3, cg = bb & 7;

        for (int i = tid; i < 18 * DIM; i += 128) {
            int p = i >> 7, d = i & (DIM - 1);
            int h = p / 9, w = p % 9;
            int nn = h * 64 + w;
            xs[p * DIM + d] = x[((size_t)b * NTOK + nn) * DIM + d];
        }
        __syncthreads();

        const int c  = cg * 64 + (tid & 63);
        const int t0 = tid >> 6;                     // tokens t0, t0+2, ..., t0+16

        float acc9[9];
        float bv = B1[c];
#pragma unroll
        for (int k = 0; k < 9; k++) acc9[k] = bv;

        for (int d4 = 0; d4 < DIM / 4; d4++) {
            float4 xv[9];
#pragma unroll
            for (int k = 0; k < 9; k++)
                xv[k] = *(const float4*)(xs + (t0 + 2 * k) * DIM + d4 * 4);
#pragma unroll
            for (int j = 0; j < 4; j++) {
                float w = W1[(size_t)(d4 * 4 + j) * HID + c];
#pragma unroll
                for (int k = 0; k < 9; k++) {
                    float xd = ((const float*)&xv[k])[j];
                    acc9[k] += xd * w;
                }
            }
        }

#pragma unroll
        for (int k = 0; k < 9; k++) {
            int p = t0 + 2 * k;
            int h = p / 9, w = p % 9;
            g_h1[(((size_t)b * 2 + h) * 9 + w) * HID + c] = acc9[k];
        }
    }
}

// ------------------------------------------------------------------
// K2: block = (batch b, j-half). Computes the 4 rows j = 4*jh .. 4*jh+3.
// conv+GELU once per channel (g_h1 reused across the 4 j), gs stored
// transposed [c][jl]; fc2 streams W2 once per block, rows packed in pairs
// into fma.rn.f32x2 accumulators. 32 blocks = 1 wave.
// ------------------------------------------------------------------
__global__ void __launch_bounds__(512) out_kernel(
    const float* __restrict__ Wd, const float* __restrict__ Bd,
    const float* __restrict__ W2, const float* __restrict__ B2,
    float* __restrict__ out)
{
    __shared__ float gs[HID * 4];                    // gs[c*4 + jl], 8 KB
    __shared__ float partial[16 * OUTD * 4];         // [slice][o][jl], 32 KB
    __shared__ unsigned mor[BATCH];

    const int tid = threadIdx.x;
    const int blk = blockIdx.x;
    const int b = blk >> 1;
    const int jbase = (blk & 1) * 4;

    // ---- mask: mor[b'] = OR over the 32 gate blocks of batch b' ----
    {
        unsigned m = __reduce_or_sync(0xffffffffu, g_bm[tid]);
        if ((tid & 31) == 0) mor[tid >> 5] = m;
    }

    // ---- conv + GELU: thread = channel c, all 4 j at once ----
    {
        const int c = tid;                           // HID == 512 == blockDim
        // v[hh][k], k = wp - (jbase-1), wp in [jbase-1, jbase+4]
        float v[2][6];
#pragma unroll
        for (int k = 0; k < 6; k++) {
            int wp = jbase - 1 + k;
            bool ok = (wp >= 0) && (wp <= 8);
#pragma unroll
            for (int hh = 0; hh < 2; hh++)
                v[hh][k] = ok ? g_h1[(((size_t)b * 2 + hh) * 9 + wp) * HID + c] : 0.0f;
        }
        float wd[2][3];
#pragma unroll
        for (int hh = 0; hh < 2; hh++)
#pragma unroll
            for (int kw = 0; kw < 3; kw++)
                wd[hh][kw] = Wd[((hh + 1) * 3 + kw) * HID + c];
        float bd = Bd[c];
#pragma unroll
        for (int jl = 0; jl < 4; jl++) {
            float conv = bd;
#pragma unroll
            for (int hh = 0; hh < 2; hh++)
#pragma unroll
                for (int kw = 0; kw < 3; kw++)
                    conv += v[hh][jl + kw] * wd[hh][kw];
            gs[c * 4 + jl] = 0.5f * conv * (1.0f + erff(conv * 0.70710678118654752f));
        }
    }
    __syncthreads();

    // ---- fc2: warp s = c-slice [32s, 32s+32); thread t = outputs 4t..4t+3;
    //      4 rows packed as 2 f32x2 accumulators per output ----
    {
        const int s = tid >> 5, t = tid & 31;
        const float* w2p = W2 + (size_t)(s * 32) * OUTD + 4 * t;
        const float* gp  = gs + (s * 32) * 4;
        unsigned long long acc[4][2];
#pragma unroll
        for (int o = 0; o < 4; o++) { acc[o][0] = 0ull; acc[o][1] = 0ull; }

#pragma unroll
        for (int i = 0; i < 32; i++) {
            ulonglong2 g2 = *(const ulonglong2*)(gp + i * 4);   // (jl0,jl1)(jl2,jl3)
            float4 w = *(const float4*)(w2p + (size_t)i * OUTD);
            float warr[4] = {w.x, w.y, w.z, w.w};
#pragma unroll
            for (int o = 0; o < 4; o++) {
                unsigned long long wd2;
                asm("mov.b64 %0, {%1, %1};" : "=l"(wd2) : "f"(warr[o]));
                FMA2(acc[o][0], g2.x, wd2);
                FMA2(acc[o][1], g2.y, wd2);
            }
        }

#pragma unroll
        for (int o = 0; o < 4; o++) {
            ulonglong2 st; st.x = acc[o][0]; st.y = acc[o][1];
            *(ulonglong2*)(partial + ((s * OUTD) + (4 * t + o)) * 4) = st;
        }
    }
    __syncthreads();

    // ---- epilogue: thread = (o, jl); reduce 16 slices + bias + gate + store ----
    {
        const int o = tid & (OUTD - 1), jl = tid >> 7;
        const int j = jbase + jl;

        float s = 0.0f;
#pragma unroll
        for (int bb = 0; bb < BATCH; bb++)
            s += g_prob0[bb * NEXP + j] * (float)((mor[bb] >> j) & 1u);
        float gv = g_prob0[b * NEXP + j] * (float)((mor[b] >> j) & 1u);
        float gate_s = gv / (s + EPS) * (float)BATCH;   // capacity = 16.0

        float acc = B2[o];
#pragma unroll
        for (int sl = 0; sl < 16; sl++)
            acc += partial[((sl * OUTD) + o) * 4 + jl];

        out[((size_t)b * NTOK + j) * OUTD + o] = gate_s * acc;
    }
}

// ------------------------------------------------------------------
extern "C" void kernel_launch(void* const* d_in, const int* in_sizes, int n_in,
                              void* d_out, int out_size)
{
    // input order: x, [H, W,] wg, bg, W1, B1, Wd, Bd, W2, B2
    int o = (n_in >= 11) ? 3 : 1;
    const float* x  = (const float*)d_in[0];
    const float* wg = (const float*)d_in[o + 0];
    const float* bg = (const float*)d_in[o + 1];
    const float* W1 = (const float*)d_in[o + 2];
    const float* B1 = (const float*)d_in[o + 3];
    const float* Wd = (const float*)d_in[o + 4];
    const float* Bd = (const float*)d_in[o + 5];
    const float* W2 = (const float*)d_in[o + 6];
    const float* B2 = (const float*)d_in[o + 7];
    float* out = (float*)d_out;

    gate_fc1_kernel<<<640, 128>>>(x, wg, bg, W1, B1, out);
    out_kernel<<<32, 512>>>(Wd, Bd, W2, B2, out);
}

// round 17
// speedup vs baseline: 1.3165x; 1.3165x over previous
#include <cuda_runtime.h>
#include <cuda_bf16.h>
#include <cuda_pipeline.h>
#include <math.h>

// SwitchMoE with the reference's dim-1 scatter gate bug:
//   mask[b, top1[b,n], 0] = 1  =>  output nonzero only for n<8, expert 0.
// E=8, DIM=128, HID=512, OUT=128, B=16, H=W=64, N=4096.
//
// Key insight this round: expert_out = fc2(gelu(dwconv(fc1(x)))) is gate-
// independent, and dwconv is depthwise (per-channel). So each fc1 block
// (batch b, 64-channel group cg) computes the FULL chain for its channels
// locally and stores fc2 partials. K2 is reduced to gate-scalar + reduce.
//
// 2 launches:
//   K1 (grid 640 x 128thr): blocks <512 = warp-autonomous gate (cp.async.cg
//       ring, FFMA2) + interleaved streaming zero-stores of out;
//       blocks >=512 = fc1+conv+GELU+fc2-partial for (b, cg).
//   K2 (grid 128 x 128thr): gate scalar + 8-partial reduce + store (tiny).

#define BATCH 16
#define NTOK  4096
#define DIM   128
#define NEXP  8
#define HID   512
#define OUTD  128
#define EPS   1e-6f

// ---- scratch (device globals; every element rewritten each call) ----
__device__ unsigned g_bm[512];                     // per-gate-block OR of (1<<argmax)
__device__ float    g_prob0[BATCH * NEXP];         // softmax p(expert0) at token n<8
__device__ float    g_part[BATCH * 8 * NEXP * OUTD];  // fc2 partials [b][cg][j][o] (512 KB)

#define FMA2(acc, a, b) \
    asm("fma.rn.f32x2 %0, %1, %2, %0;" : "+l"(acc) : "l"(a), "l"(b))

// cp.async.cg: 16B global->shared, L2-only (no L1 allocate) — streaming reads
__device__ __forceinline__ void cp_cg16(void* dst_smem, const void* src) {
    unsigned d = (unsigned)__cvta_generic_to_shared(dst_smem);
    asm volatile("cp.async.cg.shared.global [%0], [%1], 16;" :: "r"(d), "l"(src));
}

// evict-first streaming store (dead data: nobody reads the zeros back)
__device__ __forceinline__ void stg_cs_zero(float4* p) {
    asm volatile("st.global.cs.v4.f32 [%0], {%1,%1,%1,%1};" :: "l"(p), "f"(0.0f));
}

// ------------------------------------------------------------------
// K1: gate blocks + expert-chain blocks (all independent)
// ------------------------------------------------------------------
__global__ void __launch_bounds__(128, 5) gate_expert_kernel(
    const float* __restrict__ x, const float* __restrict__ wg,
    const float* __restrict__ bg, const float* __restrict__ W1,
    const float* __restrict__ B1, const float* __restrict__ Wd,
    const float* __restrict__ Bd, const float* __restrict__ W2,
    float* __restrict__ out)
{
    // pool aliasing:
    //   gate  : wg_s[1024] | bg_s[8] | xs[4 warps][4 stages][32*20] = 11272 floats
    //   expert: xs18[18*128]=2304 | h1s[18*64]=1152 | gss[64*8]=512  = 3968 floats
    __shared__ __align__(16) float pool[11272];
    __shared__ unsigned warpor[4];

    const int tid = threadIdx.x;
    const int blk = blockIdx.x;

    if (blk < 512) {
        // ================= gate path =================
        float* wg_s = pool;                          // [DIM*NEXP]
        float* bg_s = pool + 1024;                   // [NEXP]
        const int wid = tid >> 5, lane = tid & 31;
        float* xw = pool + 1032 + wid * (4 * 640);   // this warp's 4-stage ring

        const int tok0 = blk * 128;
        const float* xb = x + (size_t)(tok0 + wid * 32) * DIM;  // warp's 32 tokens
        float4* ob = (float4*)(out + (size_t)tok0 * OUTD);      // block's 128 out rows

        for (int i = tid; i < DIM * NEXP; i += 128) wg_s[i] = wg[i];
        if (tid < NEXP) bg_s[tid] = bg[tid];
        __syncthreads();                             // wg_s ready; warps go autonomous

        // staging coords: lane copies quarter q of tokens tq, tq+8, tq+16, tq+24
        const int tq = lane >> 2, q = lane & 3;

        // prologue: stage chunks 0..2 (each chunk = 32 tokens x 16 dims)
#pragma unroll
        for (int ch = 0; ch < 3; ch++) {
            float* dst = xw + ch * 640;
#pragma unroll
            for (int k = 0; k < 4; k++) {
                int t = tq + 8 * k;
                cp_cg16(dst + t * 20 + q * 4,
                        xb + (size_t)t * DIM + ch * 16 + q * 4);
            }
            __pipeline_commit();
        }

        // packed accumulators: (e0,e1) (e2,e3) (e4,e5) (e6,e7)
        unsigned long long a01 = 0ull, a23 = 0ull, a45 = 0ull, a67 = 0ull;

#pragma unroll
        for (int ch = 0; ch < 8; ch++) {
            if (ch < 5) {                            // stage chunk ch+3
                float* dst = xw + ((ch + 3) & 3) * 640;
#pragma unroll
                for (int k = 0; k < 4; k++) {
                    int t = tq + 8 * k;
                    cp_cg16(dst + t * 20 + q * 4,
                            xb + (size_t)t * DIM + (ch + 3) * 16 + q * 4);
                }
                __pipeline_commit();
                __pipeline_wait_prior(3);            // chunk ch landed
            } else {
                __pipeline_wait_prior(7 - ch);
            }
            __syncwarp();

            const float* buf = xw + (ch & 3) * 640;
#pragma unroll
            for (int d4 = 0; d4 < 4; d4++) {
                float4 xv = *(const float4*)(buf + lane * 20 + d4 * 4);
                float xarr[4] = {xv.x, xv.y, xv.z, xv.w};
#pragma unroll
                for (int jj = 0; jj < 4; jj++) {
                    int dd = ch * 16 + d4 * 4 + jj;
                    const ulonglong2* wrow = (const ulonglong2*)(wg_s + dd * 8);
                    ulonglong2 wa = wrow[0];
                    ulonglong2 wb = wrow[1];
                    unsigned long long xd2;
                    asm("mov.b64 %0, {%1, %1};" : "=l"(xd2) : "f"(xarr[jj]));
                    FMA2(a01, xd2, wa.x);
                    FMA2(a23, xd2, wa.y);
                    FMA2(a45, xd2, wb.x);
                    FMA2(a67, xd2, wb.y);
                }
            }
            __syncwarp();                            // done reading buf before re-fill

            // interleaved streaming zero-stores: 4 float4 per thread per chunk
#pragma unroll
            for (int k = 0; k < 4; k++)
                stg_cs_zero(ob + ch * 512 + k * 128 + tid);
        }

        // unpack logits, add bias; first-max argmax (matches jnp.argmax)
        float l[NEXP];
        asm("mov.b64 {%0, %1}, %2;" : "=f"(l[0]), "=f"(l[1]) : "l"(a01));
        asm("mov.b64 {%0, %1}, %2;" : "=f"(l[2]), "=f"(l[3]) : "l"(a23));
        asm("mov.b64 {%0, %1}, %2;" : "=f"(l[4]), "=f"(l[5]) : "l"(a45));
        asm("mov.b64 {%0, %1}, %2;" : "=f"(l[6]), "=f"(l[7]) : "l"(a67));
#pragma unroll
        for (int e = 0; e < NEXP; e++) l[e] += bg_s[e];
        float m = l[0]; int am = 0;
#pragma unroll
        for (int e = 1; e < NEXP; e++) if (l[e] > m) { m = l[e]; am = e; }

        const int tok = tok0 + tid;                  // wid*32+lane == tid
        const int b = tok >> 12;
        const int n = tok & (NTOK - 1);
        if (n < NEXP) {
            float s = 0.0f;
#pragma unroll
            for (int e = 0; e < NEXP; e++) s += expf(l[e] - m);
            g_prob0[b * NEXP + n] = expf(l[0] - m) / s;
        }

        // per-block argmax bitmask (replay-safe: every slot rewritten each call)
        unsigned wor = __reduce_or_sync(0xffffffffu, 1u << am);
        if (lane == 0) warpor[wid] = wor;
        __syncthreads();
        if (tid == 0)
            g_bm[blk] = warpor[0] | warpor[1] | warpor[2] | warpor[3];
    } else {
        // ========== expert path: fc1 + dwconv + GELU + fc2 partial ==========
        float* xs  = pool;                           // [18*DIM]
        float* h1s = pool + 2304;                    // [18 pixels][64 ch]
        float* gss = pool + 3456;                    // [64 ch][8 j]
        const int bb = blk - 512;                    // [0,128)
        const int b  = bb >> 3, cg = bb & 7;

        // stage the 18 needed x pixels (h in {0,1}, w in [0,9))
        for (int i = tid; i < 18 * DIM; i += 128) {
            int p = i >> 7, d = i & (DIM - 1);
            int h = p / 9, w = p % 9;
            int nn = h * 64 + w;
            xs[p * DIM + d] = x[((size_t)b * NTOK + nn) * DIM + d];
        }
        __syncthreads();

        // ---- fc1: thread = (local ch cl, pixel parity t0), 9 pixels each ----
        const int cl = tid & 63;                     // local channel
        const int C  = cg * 64 + cl;                 // global channel
        const int t0 = tid >> 6;                     // pixels t0, t0+2, ..., t0+16

        {
            float acc9[9];
            float bv = B1[C];
#pragma unroll
            for (int k = 0; k < 9; k++) acc9[k] = bv;

            for (int d4 = 0; d4 < DIM / 4; d4++) {
                float4 xv[9];
#pragma unroll
                for (int k = 0; k < 9; k++)
                    xv[k] = *(const float4*)(xs + (t0 + 2 * k) * DIM + d4 * 4);
#pragma unroll
                for (int jj = 0; jj < 4; jj++) {
                    float w = W1[(size_t)(d4 * 4 + jj) * HID + C];
#pragma unroll
                    for (int k = 0; k < 9; k++) {
                        float xd = ((const float*)&xv[k])[jj];
                        acc9[k] += xd * w;
                    }
                }
            }
#pragma unroll
            for (int k = 0; k < 9; k++)
                h1s[(t0 + 2 * k) * 64 + cl] = acc9[k];
        }
        __syncthreads();

        // ---- dwconv(3x3 SAME at h=0) + exact GELU: thread = (cl, j-half) ----
        // pixel index p = h*9 + w; kernel rows kh in {1,2} -> h' in {0,1}
        {
            const int half = t0;                     // j = half*4 .. half*4+3
            float wd[2][3];
#pragma unroll
            for (int hh = 0; hh < 2; hh++)
#pragma unroll
                for (int kw = 0; kw < 3; kw++)
                    wd[hh][kw] = Wd[((hh + 1) * 3 + kw) * HID + C];
            float bd = Bd[C];
            float4 g4;
#pragma unroll
            for (int jl = 0; jl < 4; jl++) {
                int j = half * 4 + jl;
                float conv = bd;
#pragma unroll
                for (int hh = 0; hh < 2; hh++)
#pragma unroll
                    for (int kw = 0; kw < 3; kw++) {
                        int wp = j + kw - 1;
                        if (wp >= 0 && wp <= 8)
                            conv += h1s[(hh * 9 + wp) * 64 + cl] * wd[hh][kw];
                    }
                ((float*)&g4)[jl] =
                    0.5f * conv * (1.0f + erff(conv * 0.70710678118654752f));
            }
            *(float4*)(gss + cl * 8 + half * 4) = g4;
        }
        __syncthreads();

        // ---- fc2 partial over 64 channels: thread = output o; 8 j packed ----
        {
            const int o = tid;                       // 128 outputs
            unsigned long long a01 = 0ull, a23 = 0ull, a45 = 0ull, a67 = 0ull;
            const float* w2p = W2 + (size_t)(cg * 64) * OUTD + o;
#pragma unroll 8
            for (int c = 0; c < 64; c++) {
                float w = w2p[(size_t)c * OUTD];     // coalesced across o
                unsigned long long w2;
                asm("mov.b64 %0, {%1, %1};" : "=l"(w2) : "f"(w));
                ulonglong2 gA = *(const ulonglong2*)(gss + c * 8);      // j0..3
                ulonglong2 gB = *(const ulonglong2*)(gss + c * 8 + 4);  // j4..7
                FMA2(a01, gA.x, w2);
                FMA2(a23, gA.y, w2);
                FMA2(a45, gB.x, w2);
                FMA2(a67, gB.y, w2);
            }
            float pj[8];
            asm("mov.b64 {%0, %1}, %2;" : "=f"(pj[0]), "=f"(pj[1]) : "l"(a01));
            asm("mov.b64 {%0, %1}, %2;" : "=f"(pj[2]), "=f"(pj[3]) : "l"(a23));
            asm("mov.b64 {%0, %1}, %2;" : "=f"(pj[4]), "=f"(pj[5]) : "l"(a45));
            asm("mov.b64 {%0, %1}, %2;" : "=f"(pj[6]), "=f"(pj[7]) : "l"(a67));
            float* gp = g_part + (((size_t)b * 8 + cg) * NEXP) * OUTD + o;
#pragma unroll
            for (int j = 0; j < 8; j++)
                gp[j * OUTD] = pj[j];                // coalesced across o
        }
    }
}

// ------------------------------------------------------------------
// K2: tiny gating kernel. Block = (b, j): gate scalar from g_bm/g_prob0,
// reduce the 8 fc2 partials + B2, single store of the row.
// ------------------------------------------------------------------
__global__ void __launch_bounds__(128) gate_out_kernel(
    const float* __restrict__ B2, float* __restrict__ out)
{
    const int tid = threadIdx.x;
    const int blk = blockIdx.x;
    const int b = blk >> 3, j = blk & 7;
    const int wid = tid >> 5, lane = tid & 31;

    __shared__ unsigned mor[BATCH];

    // mor[b'] = OR over the 32 gate blocks of batch b'; warp w does b' = w+4k
#pragma unroll
    for (int k = 0; k < 4; k++) {
        int bb = wid + 4 * k;
        unsigned m = __reduce_or_sync(0xffffffffu, g_bm[bb * 32 + lane]);
        if (lane == 0) mor[bb] = m;
    }
    __syncthreads();

    // gate scalar (uniform; broadcast loads)
    float s = 0.0f;
#pragma unroll
    for (int bb = 0; bb < BATCH; bb++)
        s += g_prob0[bb * NEXP + j] * (float)((mor[bb] >> j) & 1u);
    float gv = g_prob0[b * NEXP + j] * (float)((mor[b] >> j) & 1u);
    float gate_s = gv / (s + EPS) * (float)BATCH;    // capacity = 16.0

    // reduce 8 partials + bias, store row (b, n=j)
    float acc = B2[tid];
    const float* gp = g_part + (((size_t)b * 8) * NEXP + j) * OUTD + tid;
#pragma unroll
    for (int cg = 0; cg < 8; cg++)
        acc += gp[cg * NEXP * OUTD];                 // coalesced across tid

    out[((size_t)b * NTOK + j) * OUTD + tid] = gate_s * acc;
}

// ------------------------------------------------------------------
extern "C" void kernel_launch(void* const* d_in, const int* in_sizes, int n_in,
                              void* d_out, int out_size)
{
    // input order: x, [H, W,] wg, bg, W1, B1, Wd, Bd, W2, B2
    int o = (n_in >= 11) ? 3 : 1;
    const float* x  = (const float*)d_in[0];
    const float* wg = (const float*)d_in[o + 0];
    const float* bg = (const float*)d_in[o + 1];
    const float* W1 = (const float*)d_in[o + 2];
    const float* B1 = (const float*)d_in[o + 3];
    const float* Wd = (const float*)d_in[o + 4];
    const float* Bd = (const float*)d_in[o + 5];
    const float* W2 = (const float*)d_in[o + 6];
    const float* B2 = (const float*)d_in[o + 7];
    float* out = (float*)d_out;

    gate_expert_kernel<<<640, 128>>>(x, wg, bg, W1, B1, Wd, Bd, W2, out);
    gate_out_kernel<<<128, 128>>>(B2, out);
}